// round 9
// baseline (speedup 1.0000x reference)
#include <cuda_runtime.h>
#include <stdint.h>

#define NN     100000
#define INC    256
#define HIDC   64
#define OC     40
#define MAXD1  64
#define MAXD2  80
#define OVFMAX 65536

static __device__ float g_h0[(size_t)NN * HIDC];
static __device__ float g_g1[(size_t)NN * OC];
static __device__ float g_g2[(size_t)NN * OC];
static __device__ int   g_cnt1[NN];
static __device__ int   g_cnt2[NN];
static __device__ int2  g_slot1[(size_t)NN * MAXD1];   // (col, val-bits)
static __device__ int2  g_slot2[(size_t)NN * MAXD2];
static __device__ int   g_ovf_n;
static __device__ int4  g_ovf[OVFMAX];                 // (graph, row, col, val-bits)

// ---------------- packed fp32 helpers (FFMA2 via PTX fma.rn.f32x2) ----------
__device__ __forceinline__ unsigned long long fma2(unsigned long long a,
                                                   unsigned long long b,
                                                   unsigned long long c) {
    unsigned long long d;
    asm("fma.rn.f32x2 %0, %1, %2, %3;" : "=l"(d) : "l"(a), "l"(b), "l"(c));
    return d;
}
__device__ __forceinline__ unsigned long long dup2(float x) {
    unsigned long long d;
    asm("mov.b64 %0, {%1, %1};" : "=l"(d) : "f"(x));
    return d;
}
__device__ __forceinline__ float2 unpk(unsigned long long v) {
    float2 r;
    asm("mov.b64 {%0, %1}, %2;" : "=f"(r.x), "=f"(r.y) : "l"(v));
    return r;
}

// ---------------------------------------------------------------------------
// GEMM1v2: h0 = x @ fc1_w^T   x[NN,256], w[64,256] -> g_h0[NN,64]
// Tile 256 rows x 64 cols; thread = 8 rows x 8 cols; per k4: 16 LDS -> 128 FFMA2.
// bb double-buffered across k4.
// ---------------------------------------------------------------------------
__global__ __launch_bounds__(256, 2) void gemm1(const float* __restrict__ x,
                                                const float* __restrict__ w) {
    __shared__ __align__(16) float xs[256][36];    // [row][k-chunk]
    __shared__ __align__(16) float ws_t[32][68];   // [k][n]
    const int tid = threadIdx.x;
    const int tx = tid & 7;        // cols tx*8 .. tx*8+7
    const int ty = tid >> 3;       // rows ty*8 .. ty*8+7
    const int row0 = blockIdx.x * 256;

    unsigned long long acc[8][4];
#pragma unroll
    for (int i = 0; i < 8; i++)
#pragma unroll
        for (int j = 0; j < 4; j++) acc[i][j] = 0ULL;

    for (int k0 = 0; k0 < INC; k0 += 32) {
        // stage x tile: 256 rows x 8 float4, k4-fast (coalesced)
#pragma unroll
        for (int q = 0; q < 8; q++) {
            int f  = tid + q * 256;
            int k4 = f & 7;
            int r  = f >> 3;
            int gr = min(row0 + r, NN - 1);
            float4 xv = *reinterpret_cast<const float4*>(x + (size_t)gr * INC + k0 + k4 * 4);
            *reinterpret_cast<float4*>(&xs[r][k4 * 4]) = xv;
        }
        // stage w tile transposed: 64 n x 8 float4
#pragma unroll
        for (int q = 0; q < 2; q++) {
            int f  = tid + q * 256;
            int k4 = f & 7;
            int n  = f >> 3;
            float4 wv = *reinterpret_cast<const float4*>(w + (size_t)n * INC + k0 + k4 * 4);
            ws_t[k4 * 4 + 0][n] = wv.x;
            ws_t[k4 * 4 + 1][n] = wv.y;
            ws_t[k4 * 4 + 2][n] = wv.z;
            ws_t[k4 * 4 + 3][n] = wv.w;
        }
        __syncthreads();

        ulonglong2 bbc[4][2];
#pragma unroll
        for (int k = 0; k < 4; k++) {
            bbc[k][0] = *reinterpret_cast<const ulonglong2*>(&ws_t[k][tx * 8]);
            bbc[k][1] = *reinterpret_cast<const ulonglong2*>(&ws_t[k][tx * 8 + 4]);
        }
#pragma unroll
        for (int k4 = 0; k4 < 8; k4++) {
            ulonglong2 bbn[4][2];
            if (k4 < 7) {
#pragma unroll
                for (int k = 0; k < 4; k++) {
                    bbn[k][0] = *reinterpret_cast<const ulonglong2*>(&ws_t[(k4 + 1) * 4 + k][tx * 8]);
                    bbn[k][1] = *reinterpret_cast<const ulonglong2*>(&ws_t[(k4 + 1) * 4 + k][tx * 8 + 4]);
                }
            }
#pragma unroll
            for (int i = 0; i < 8; i++) {
                float4 a4 = *reinterpret_cast<const float4*>(&xs[ty * 8 + i][k4 * 4]);
                unsigned long long aa;
                aa = dup2(a4.x);
                acc[i][0] = fma2(aa, bbc[0][0].x, acc[i][0]);
                acc[i][1] = fma2(aa, bbc[0][0].y, acc[i][1]);
                acc[i][2] = fma2(aa, bbc[0][1].x, acc[i][2]);
                acc[i][3] = fma2(aa, bbc[0][1].y, acc[i][3]);
                aa = dup2(a4.y);
                acc[i][0] = fma2(aa, bbc[1][0].x, acc[i][0]);
                acc[i][1] = fma2(aa, bbc[1][0].y, acc[i][1]);
                acc[i][2] = fma2(aa, bbc[1][1].x, acc[i][2]);
                acc[i][3] = fma2(aa, bbc[1][1].y, acc[i][3]);
                aa = dup2(a4.z);
                acc[i][0] = fma2(aa, bbc[2][0].x, acc[i][0]);
                acc[i][1] = fma2(aa, bbc[2][0].y, acc[i][1]);
                acc[i][2] = fma2(aa, bbc[2][1].x, acc[i][2]);
                acc[i][3] = fma2(aa, bbc[2][1].y, acc[i][3]);
                aa = dup2(a4.w);
                acc[i][0] = fma2(aa, bbc[3][0].x, acc[i][0]);
                acc[i][1] = fma2(aa, bbc[3][0].y, acc[i][1]);
                acc[i][2] = fma2(aa, bbc[3][1].x, acc[i][2]);
                acc[i][3] = fma2(aa, bbc[3][1].y, acc[i][3]);
            }
            if (k4 < 7) {
#pragma unroll
                for (int k = 0; k < 4; k++) {
                    bbc[k][0] = bbn[k][0];
                    bbc[k][1] = bbn[k][1];
                }
            }
        }
        __syncthreads();
    }
#pragma unroll
    for (int i = 0; i < 8; i++) {
        int gr = row0 + ty * 8 + i;
        if (gr < NN) {
            float2 p0 = unpk(acc[i][0]);
            float2 p1 = unpk(acc[i][1]);
            float2 p2 = unpk(acc[i][2]);
            float2 p3 = unpk(acc[i][3]);
            *reinterpret_cast<float4*>(g_h0 + (size_t)gr * HIDC + tx * 8) =
                make_float4(p0.x, p0.y, p1.x, p1.y);
            *reinterpret_cast<float4*>(g_h0 + (size_t)gr * HIDC + tx * 8 + 4) =
                make_float4(p2.x, p2.y, p3.x, p3.y);
        }
    }
}

// ---------------------------------------------------------------------------
// PROJ2v2: block = 64 rows x 128 cols (120 real), thread = 4 rows x 8 cols.
// cols [0:40)=out(+bias), [40:80)=g1, [80:120)=g2, [120:128)=pad.
// 3 blocks/SM (occ 37.5%), bb double-buffered.
// ---------------------------------------------------------------------------
__global__ __launch_bounds__(256, 3) void proj2(const float* __restrict__ w,
                                                const float* __restrict__ b,
                                                float* __restrict__ out) {
    __shared__ __align__(16) float hs[64][68];     // [row][k]
    __shared__ __align__(16) float wt[64][132];    // [k][col]
    __shared__ float bs[OC];
    const int tid = threadIdx.x;
    const int row0 = blockIdx.x * 64;

    for (int idx = tid; idx < 64 * 128; idx += 256) {
        int k = idx >> 7;
        int c = idx & 127;
        float val = 0.f;
        if (c < 120) {
            int o = c % 40;
            int s = c / 40;
            val = w[o * 192 + s * 64 + k];
        }
        wt[k][c] = val;
    }
    if (tid < OC) bs[tid] = b[tid];
#pragma unroll
    for (int q = 0; q < 4; q++) {
        int f  = tid + q * 256;
        int k4 = f & 15;
        int r  = f >> 4;
        int gr = min(row0 + r, NN - 1);
        *reinterpret_cast<float4*>(&hs[r][k4 * 4]) =
            *reinterpret_cast<const float4*>(g_h0 + (size_t)gr * HIDC + k4 * 4);
    }
    __syncthreads();

    const int tx = tid & 15;       // cols tx*8 .. tx*8+7
    const int ty = tid >> 4;       // rows ty*4 .. ty*4+3

    unsigned long long acc[4][4];
#pragma unroll
    for (int i = 0; i < 4; i++)
#pragma unroll
        for (int j = 0; j < 4; j++) acc[i][j] = 0ULL;

    ulonglong2 bbc[4][2];
#pragma unroll
    for (int k = 0; k < 4; k++) {
        bbc[k][0] = *reinterpret_cast<const ulonglong2*>(&wt[k][tx * 8]);
        bbc[k][1] = *reinterpret_cast<const ulonglong2*>(&wt[k][tx * 8 + 4]);
    }
#pragma unroll
    for (int k4 = 0; k4 < 16; k4++) {
        ulonglong2 bbn[4][2];
        if (k4 < 15) {
#pragma unroll
            for (int k = 0; k < 4; k++) {
                bbn[k][0] = *reinterpret_cast<const ulonglong2*>(&wt[(k4 + 1) * 4 + k][tx * 8]);
                bbn[k][1] = *reinterpret_cast<const ulonglong2*>(&wt[(k4 + 1) * 4 + k][tx * 8 + 4]);
            }
        }
#pragma unroll
        for (int i = 0; i < 4; i++) {
            float4 a4 = *reinterpret_cast<const float4*>(&hs[ty * 4 + i][k4 * 4]);
            unsigned long long aa;
            aa = dup2(a4.x);
            acc[i][0] = fma2(aa, bbc[0][0].x, acc[i][0]);
            acc[i][1] = fma2(aa, bbc[0][0].y, acc[i][1]);
            acc[i][2] = fma2(aa, bbc[0][1].x, acc[i][2]);
            acc[i][3] = fma2(aa, bbc[0][1].y, acc[i][3]);
            aa = dup2(a4.y);
            acc[i][0] = fma2(aa, bbc[1][0].x, acc[i][0]);
            acc[i][1] = fma2(aa, bbc[1][0].y, acc[i][1]);
            acc[i][2] = fma2(aa, bbc[1][1].x, acc[i][2]);
            acc[i][3] = fma2(aa, bbc[1][1].y, acc[i][3]);
            aa = dup2(a4.z);
            acc[i][0] = fma2(aa, bbc[2][0].x, acc[i][0]);
            acc[i][1] = fma2(aa, bbc[2][0].y, acc[i][1]);
            acc[i][2] = fma2(aa, bbc[2][1].x, acc[i][2]);
            acc[i][3] = fma2(aa, bbc[2][1].y, acc[i][3]);
            aa = dup2(a4.w);
            acc[i][0] = fma2(aa, bbc[3][0].x, acc[i][0]);
            acc[i][1] = fma2(aa, bbc[3][0].y, acc[i][1]);
            acc[i][2] = fma2(aa, bbc[3][1].x, acc[i][2]);
            acc[i][3] = fma2(aa, bbc[3][1].y, acc[i][3]);
        }
        if (k4 < 15) {
#pragma unroll
            for (int k = 0; k < 4; k++) {
                bbc[k][0] = bbn[k][0];
                bbc[k][1] = bbn[k][1];
            }
        }
    }

    if (tx < 15) {
        const int c0 = tx * 8;
        const int s  = c0 / 40;
        const int cb = c0 - s * 40;
        float* base = (s == 0) ? out : (s == 1) ? g_g1 : g_g2;
#pragma unroll
        for (int i = 0; i < 4; i++) {
            int gr = row0 + ty * 4 + i;
            if (gr < NN) {
                float2 p0 = unpk(acc[i][0]);
                float2 p1 = unpk(acc[i][1]);
                float2 p2 = unpk(acc[i][2]);
                float2 p3 = unpk(acc[i][3]);
                float4 v0 = make_float4(p0.x, p0.y, p1.x, p1.y);
                float4 v1 = make_float4(p2.x, p2.y, p3.x, p3.y);
                if (s == 0) {
                    v0.x += bs[cb + 0]; v0.y += bs[cb + 1];
                    v0.z += bs[cb + 2]; v0.w += bs[cb + 3];
                    v1.x += bs[cb + 4]; v1.y += bs[cb + 5];
                    v1.z += bs[cb + 6]; v1.w += bs[cb + 7];
                }
                *reinterpret_cast<float4*>(base + (size_t)gr * OC + cb)     = v0;
                *reinterpret_cast<float4*>(base + (size_t)gr * OC + cb + 4) = v1;
            }
        }
    }
}

// ---------------------------------------------------------------------------
// Binning: zero counters -> scatter edges into fixed-stride per-row bins.
// ---------------------------------------------------------------------------
__global__ void zero_cnt() {
    int i = blockIdx.x * blockDim.x + threadIdx.x;
    if (i < NN)          g_cnt1[i] = 0;
    else if (i < 2 * NN) g_cnt2[i - NN] = 0;
    if (i == 0) g_ovf_n = 0;
}

__global__ void scatter(const int* __restrict__ r1, const int* __restrict__ c1,
                        const float* __restrict__ v1, int E1,
                        const int* __restrict__ r2, const int* __restrict__ c2,
                        const float* __restrict__ v2, int E2) {
    int i = blockIdx.x * blockDim.x + threadIdx.x;
    if (i < E1) {
        int r = __ldg(r1 + i);
        int c = __ldg(c1 + i);
        int v = __float_as_int(__ldg(v1 + i));
        int p = atomicAdd(&g_cnt1[r], 1);
        if (p < MAXD1) {
            g_slot1[(size_t)r * MAXD1 + p] = make_int2(c, v);
        } else {
            int o = atomicAdd(&g_ovf_n, 1);
            if (o < OVFMAX) g_ovf[o] = make_int4(0, r, c, v);
        }
    } else if (i < E1 + E2) {
        int j = i - E1;
        int r = __ldg(r2 + j);
        int c = __ldg(c2 + j);
        int v = __float_as_int(__ldg(v2 + j));
        int p = atomicAdd(&g_cnt2[r], 1);
        if (p < MAXD2) {
            g_slot2[(size_t)r * MAXD2 + p] = make_int2(c, v);
        } else {
            int o = atomicAdd(&g_ovf_n, 1);
            if (o < OVFMAX) g_ovf[o] = make_int4(1, r, c, v);
        }
    }
}

// ---------------------------------------------------------------------------
// GATHER: 2 warps per row (one per graph). Warp: 3 edges x 10 float4-lanes,
// unroll-2. Capture-first 3-way shfl combine, then one 10-lane red.v4.
// ---------------------------------------------------------------------------
__global__ __launch_bounds__(256) void gather(float* __restrict__ out) {
    const int w = (int)((blockIdx.x * blockDim.x + threadIdx.x) >> 5);
    if (w >= 2 * NN) return;
    const int r = w >> 1;
    const int g = w & 1;

    const int2*  slots;
    const float* G;
    int cnt;
    if (g == 0) {
        slots = g_slot1 + (size_t)r * MAXD1;
        G     = g_g1;
        cnt   = min(__ldg(&g_cnt1[r]), MAXD1);
    } else {
        slots = g_slot2 + (size_t)r * MAXD2;
        G     = g_g2;
        cnt   = min(__ldg(&g_cnt2[r]), MAXD2);
    }

    const int lane = threadIdx.x & 31;
    const int grp  = lane / 10;
    const int slot = lane - grp * 10;
    const bool act = lane < 30;

    float4 acc = make_float4(0.f, 0.f, 0.f, 0.f);
    if (act) {
        int e = grp;
        for (; e + 3 < cnt; e += 6) {
            int2 ea = __ldg(slots + e);
            int2 eb = __ldg(slots + e + 3);
            float4 ha = __ldg(reinterpret_cast<const float4*>(
                              G + (size_t)ea.x * OC + slot * 4));
            float4 hb = __ldg(reinterpret_cast<const float4*>(
                              G + (size_t)eb.x * OC + slot * 4));
            float va = __int_as_float(ea.y);
            float vb = __int_as_float(eb.y);
            acc.x += va * ha.x + vb * hb.x;
            acc.y += va * ha.y + vb * hb.y;
            acc.z += va * ha.z + vb * hb.z;
            acc.w += va * ha.w + vb * hb.w;
        }
        if (e < cnt) {
            int2 ea = __ldg(slots + e);
            float4 ha = __ldg(reinterpret_cast<const float4*>(
                              G + (size_t)ea.x * OC + slot * 4));
            float va = __int_as_float(ea.y);
            acc.x += va * ha.x; acc.y += va * ha.y;
            acc.z += va * ha.z; acc.w += va * ha.w;
        }
    }
    float4 b1, b2;
    b1.x = __shfl_down_sync(0xffffffffu, acc.x, 10);
    b1.y = __shfl_down_sync(0xffffffffu, acc.y, 10);
    b1.z = __shfl_down_sync(0xffffffffu, acc.z, 10);
    b1.w = __shfl_down_sync(0xffffffffu, acc.w, 10);
    b2.x = __shfl_down_sync(0xffffffffu, acc.x, 20);
    b2.y = __shfl_down_sync(0xffffffffu, acc.y, 20);
    b2.z = __shfl_down_sync(0xffffffffu, acc.z, 20);
    b2.w = __shfl_down_sync(0xffffffffu, acc.w, 20);

    if (lane < 10) {
        float* dst = out + (size_t)r * OC + slot * 4;
        float4 s = make_float4(acc.x + b1.x + b2.x, acc.y + b1.y + b2.y,
                               acc.z + b1.z + b2.z, acc.w + b1.w + b2.w);
        asm volatile("red.global.add.v4.f32 [%0], {%1,%2,%3,%4};"
                     :: "l"(dst), "f"(s.x), "f"(s.y), "f"(s.z), "f"(s.w)
                     : "memory");
    }
}

// ---------------------------------------------------------------------------
// FIXUP: process overflow edges (normally zero of them).
// ---------------------------------------------------------------------------
__global__ void fixup(float* __restrict__ out) {
    int n = g_ovf_n;
    if (n > OVFMAX) n = OVFMAX;
    for (int i = threadIdx.x; i < n; i += blockDim.x) {
        int4 e = g_ovf[i];
        const float* G = e.x ? g_g2 : g_g1;
        float v = __int_as_float(e.w);
        for (int j = 0; j < OC; j++) {
            float p = v * G[(size_t)e.z * OC + j];
            asm volatile("red.global.add.f32 [%0], %1;"
                         :: "l"(out + (size_t)e.y * OC + j), "f"(p) : "memory");
        }
    }
}

// ---------------------------------------------------------------------------
// Launch with capture fork: [zero+scatter] || [gemm1+proj2]; join; gather.
// ---------------------------------------------------------------------------
extern "C" void kernel_launch(void* const* d_in, const int* in_sizes, int n_in,
                              void* d_out, int out_size) {
    const float* x   = (const float*)d_in[0];
    const int*   a1r = (const int*)  d_in[2];
    const int*   a1c = (const int*)  d_in[3];
    const float* a1v = (const float*)d_in[4];
    const int*   a2r = (const int*)  d_in[5];
    const int*   a2c = (const int*)  d_in[6];
    const float* a2v = (const float*)d_in[7];
    const float* w1  = (const float*)d_in[8];
    const float* w2  = (const float*)d_in[9];
    const float* b2  = (const float*)d_in[10];
    float* out = (float*)d_out;
    const int E1 = in_sizes[4];
    const int E2 = in_sizes[7];
    const int Et = E1 + E2;

    cudaStream_t s2;
    cudaEvent_t  e0, e1;
    cudaStreamCreateWithFlags(&s2, cudaStreamNonBlocking);
    cudaEventCreateWithFlags(&e0, cudaEventDisableTiming);
    cudaEventCreateWithFlags(&e1, cudaEventDisableTiming);

    cudaEventRecord(e0, 0);
    cudaStreamWaitEvent(s2, e0, 0);
    zero_cnt<<<(2 * NN + 255) / 256, 256, 0, s2>>>();
    scatter<<<(Et + 255) / 256, 256, 0, s2>>>(a1r, a1c, a1v, E1,
                                              a2r, a2c, a2v, E2);
    cudaEventRecord(e1, s2);

    gemm1<<<(NN + 255) / 256, 256>>>(x, w1);
    proj2<<<(NN + 63) / 64, 256>>>(w2, b2, out);

    cudaStreamWaitEvent(0, e1, 0);
    gather<<<(2 * NN * 32 + 255) / 256, 256>>>(out);
    fixup<<<1, 256>>>(out);

    cudaStreamDestroy(s2);
    cudaEventDestroy(e0);
    cudaEventDestroy(e1);
}

// round 10
// speedup vs baseline: 1.0847x; 1.0847x over previous
#include <cuda_runtime.h>
#include <stdint.h>

#define NN     100000
#define INC    256
#define OC     40
#define NC     128      // padded fused output cols (120 real)
#define MAXD1  64
#define MAXD2  80
#define OVFMAX 65536

static __device__ float g_g1[(size_t)NN * OC];
static __device__ float g_g2[(size_t)NN * OC];
static __device__ __align__(16) float g_wf[(size_t)INC * NC];  // fused W, [k][c]
static __device__ int   g_cnt1[NN];
static __device__ int   g_cnt2[NN];
static __device__ int2  g_slot1[(size_t)NN * MAXD1];   // (col, val-bits)
static __device__ int2  g_slot2[(size_t)NN * MAXD2];
static __device__ int   g_ovf_n;
static __device__ int4  g_ovf[OVFMAX];                 // (graph, row, col, val-bits)

// ---------------- packed fp32 helpers (FFMA2 via PTX fma.rn.f32x2) ----------
__device__ __forceinline__ unsigned long long fma2(unsigned long long a,
                                                   unsigned long long b,
                                                   unsigned long long c) {
    unsigned long long d;
    asm("fma.rn.f32x2 %0, %1, %2, %3;" : "=l"(d) : "l"(a), "l"(b), "l"(c));
    return d;
}
__device__ __forceinline__ unsigned long long dup2(float x) {
    unsigned long long d;
    asm("mov.b64 %0, {%1, %1};" : "=l"(d) : "f"(x));
    return d;
}
__device__ __forceinline__ float2 unpk(unsigned long long v) {
    float2 r;
    asm("mov.b64 {%0, %1}, %2;" : "=f"(r.x), "=f"(r.y) : "l"(v));
    return r;
}

// ---------------------------------------------------------------------------
// FUSE_W: g_wf[k][c] = sum_j fc_out_w[o, s*64+j] * fc1_w[j, k]
//   where c -> (s = c/40, o = c%40), c in [0,120); pad cols [120,128) = 0.
// Block c = blockIdx.x, thread k = tid. fc1_w row loads coalesced.
// ---------------------------------------------------------------------------
__global__ __launch_bounds__(256) void fuse_w(const float* __restrict__ w1,
                                              const float* __restrict__ w2) {
    const int c = blockIdx.x;      // 0..127
    const int k = threadIdx.x;     // 0..255
    float acc = 0.f;
    if (c < 120) {
        const int o = c % 40;
        const int s = c / 40;
        const float* wrow = w2 + o * 192 + s * 64;
#pragma unroll 8
        for (int j = 0; j < 64; j++)
            acc = fmaf(__ldg(wrow + j), __ldg(w1 + j * INC + k), acc);
    }
    g_wf[(size_t)k * NC + c] = acc;
}

// ---------------------------------------------------------------------------
// BIGGEMM: [out | g1 | g2] = x @ Wf^T + [b|0|0]
// Tile 128 rows x 128 cols, thread = 8x8, K-chunk 32, bb double-buffered.
// Weight staging coalesced float4 from k-major g_wf.
// ---------------------------------------------------------------------------
__global__ __launch_bounds__(256, 2) void biggemm(const float* __restrict__ x,
                                                  const float* __restrict__ b,
                                                  float* __restrict__ out) {
    __shared__ __align__(16) float xs[128][36];    // [row][k-chunk]
    __shared__ __align__(16) float wt[32][132];    // [k][col]
    __shared__ float bs[OC];
    const int tid = threadIdx.x;
    const int tx = tid & 15;       // cols tx*8 .. tx*8+7
    const int ty = tid >> 4;       // rows ty*8 .. ty*8+7
    const int row0 = blockIdx.x * 128;
    if (tid < OC) bs[tid] = b[tid];

    unsigned long long acc[8][4];
#pragma unroll
    for (int i = 0; i < 8; i++)
#pragma unroll
        for (int j = 0; j < 4; j++) acc[i][j] = 0ULL;

    for (int k0 = 0; k0 < INC; k0 += 32) {
        // stage x tile: 128 rows x 8 float4, k4-fast (coalesced)
#pragma unroll
        for (int q = 0; q < 4; q++) {
            int f  = tid + q * 256;
            int k4 = f & 7;
            int r  = f >> 3;
            int gr = min(row0 + r, NN - 1);
            float4 xv = *reinterpret_cast<const float4*>(x + (size_t)gr * INC + k0 + k4 * 4);
            *reinterpret_cast<float4*>(&xs[r][k4 * 4]) = xv;
        }
        // stage weight chunk: 32 k x 128 c, fully coalesced float4
#pragma unroll
        for (int q = 0; q < 4; q++) {
            int f  = tid + q * 256;
            int c4 = f & 31;
            int kk = f >> 5;
            float4 wv = *reinterpret_cast<const float4*>(
                g_wf + (size_t)(k0 + kk) * NC + c4 * 4);
            *reinterpret_cast<float4*>(&wt[kk][c4 * 4]) = wv;
        }
        __syncthreads();

        ulonglong2 bbc[4][2];
#pragma unroll
        for (int k = 0; k < 4; k++) {
            bbc[k][0] = *reinterpret_cast<const ulonglong2*>(&wt[k][tx * 8]);
            bbc[k][1] = *reinterpret_cast<const ulonglong2*>(&wt[k][tx * 8 + 4]);
        }
#pragma unroll
        for (int k4 = 0; k4 < 8; k4++) {
            ulonglong2 bbn[4][2];
            if (k4 < 7) {
#pragma unroll
                for (int k = 0; k < 4; k++) {
                    bbn[k][0] = *reinterpret_cast<const ulonglong2*>(&wt[(k4 + 1) * 4 + k][tx * 8]);
                    bbn[k][1] = *reinterpret_cast<const ulonglong2*>(&wt[(k4 + 1) * 4 + k][tx * 8 + 4]);
                }
            }
#pragma unroll
            for (int i = 0; i < 8; i++) {
                float4 a4 = *reinterpret_cast<const float4*>(&xs[ty * 8 + i][k4 * 4]);
                unsigned long long aa;
                aa = dup2(a4.x);
                acc[i][0] = fma2(aa, bbc[0][0].x, acc[i][0]);
                acc[i][1] = fma2(aa, bbc[0][0].y, acc[i][1]);
                acc[i][2] = fma2(aa, bbc[0][1].x, acc[i][2]);
                acc[i][3] = fma2(aa, bbc[0][1].y, acc[i][3]);
                aa = dup2(a4.y);
                acc[i][0] = fma2(aa, bbc[1][0].x, acc[i][0]);
                acc[i][1] = fma2(aa, bbc[1][0].y, acc[i][1]);
                acc[i][2] = fma2(aa, bbc[1][1].x, acc[i][2]);
                acc[i][3] = fma2(aa, bbc[1][1].y, acc[i][3]);
                aa = dup2(a4.z);
                acc[i][0] = fma2(aa, bbc[2][0].x, acc[i][0]);
                acc[i][1] = fma2(aa, bbc[2][0].y, acc[i][1]);
                acc[i][2] = fma2(aa, bbc[2][1].x, acc[i][2]);
                acc[i][3] = fma2(aa, bbc[2][1].y, acc[i][3]);
                aa = dup2(a4.w);
                acc[i][0] = fma2(aa, bbc[3][0].x, acc[i][0]);
                acc[i][1] = fma2(aa, bbc[3][0].y, acc[i][1]);
                acc[i][2] = fma2(aa, bbc[3][1].x, acc[i][2]);
                acc[i][3] = fma2(aa, bbc[3][1].y, acc[i][3]);
            }
            if (k4 < 7) {
#pragma unroll
                for (int k = 0; k < 4; k++) {
                    bbc[k][0] = bbn[k][0];
                    bbc[k][1] = bbn[k][1];
                }
            }
        }
        __syncthreads();
    }

    if (tx < 15) {                         // tx==15 = pad cols, discard
        const int c0 = tx * 8;
        const int s  = c0 / 40;            // 8-col group never straddles a segment
        const int cb = c0 - s * 40;
        float* base = (s == 0) ? out : (s == 1) ? g_g1 : g_g2;
#pragma unroll
        for (int i = 0; i < 8; i++) {
            int gr = row0 + ty * 8 + i;
            if (gr < NN) {
                float2 p0 = unpk(acc[i][0]);
                float2 p1 = unpk(acc[i][1]);
                float2 p2 = unpk(acc[i][2]);
                float2 p3 = unpk(acc[i][3]);
                float4 v0 = make_float4(p0.x, p0.y, p1.x, p1.y);
                float4 v1 = make_float4(p2.x, p2.y, p3.x, p3.y);
                if (s == 0) {
                    v0.x += bs[cb + 0]; v0.y += bs[cb + 1];
                    v0.z += bs[cb + 2]; v0.w += bs[cb + 3];
                    v1.x += bs[cb + 4]; v1.y += bs[cb + 5];
                    v1.z += bs[cb + 6]; v1.w += bs[cb + 7];
                }
                *reinterpret_cast<float4*>(base + (size_t)gr * OC + cb)     = v0;
                *reinterpret_cast<float4*>(base + (size_t)gr * OC + cb + 4) = v1;
            }
        }
    }
}

// ---------------------------------------------------------------------------
// Binning: zero counters -> scatter edges into fixed-stride per-row bins.
// ---------------------------------------------------------------------------
__global__ void zero_cnt() {
    int i = blockIdx.x * blockDim.x + threadIdx.x;
    if (i < NN)          g_cnt1[i] = 0;
    else if (i < 2 * NN) g_cnt2[i - NN] = 0;
    if (i == 0) g_ovf_n = 0;
}

__global__ void scatter(const int* __restrict__ r1, const int* __restrict__ c1,
                        const float* __restrict__ v1, int E1,
                        const int* __restrict__ r2, const int* __restrict__ c2,
                        const float* __restrict__ v2, int E2) {
    int i = blockIdx.x * blockDim.x + threadIdx.x;
    if (i < E1) {
        int r = __ldg(r1 + i);
        int c = __ldg(c1 + i);
        int v = __float_as_int(__ldg(v1 + i));
        int p = atomicAdd(&g_cnt1[r], 1);
        if (p < MAXD1) {
            g_slot1[(size_t)r * MAXD1 + p] = make_int2(c, v);
        } else {
            int o = atomicAdd(&g_ovf_n, 1);
            if (o < OVFMAX) g_ovf[o] = make_int4(0, r, c, v);
        }
    } else if (i < E1 + E2) {
        int j = i - E1;
        int r = __ldg(r2 + j);
        int c = __ldg(c2 + j);
        int v = __float_as_int(__ldg(v2 + j));
        int p = atomicAdd(&g_cnt2[r], 1);
        if (p < MAXD2) {
            g_slot2[(size_t)r * MAXD2 + p] = make_int2(c, v);
        } else {
            int o = atomicAdd(&g_ovf_n, 1);
            if (o < OVFMAX) g_ovf[o] = make_int4(1, r, c, v);
        }
    }
}

// ---------------------------------------------------------------------------
// GATHER: 2 warps per row (one per graph). Warp: 3 edges x 10 float4-lanes,
// unroll-2. Capture-first 3-way shfl combine, then one 10-lane red.v4.
// ---------------------------------------------------------------------------
__global__ __launch_bounds__(256) void gather(float* __restrict__ out) {
    const int w = (int)((blockIdx.x * blockDim.x + threadIdx.x) >> 5);
    if (w >= 2 * NN) return;
    const int r = w >> 1;
    const int g = w & 1;

    const int2*  slots;
    const float* G;
    int cnt;
    if (g == 0) {
        slots = g_slot1 + (size_t)r * MAXD1;
        G     = g_g1;
        cnt   = min(__ldg(&g_cnt1[r]), MAXD1);
    } else {
        slots = g_slot2 + (size_t)r * MAXD2;
        G     = g_g2;
        cnt   = min(__ldg(&g_cnt2[r]), MAXD2);
    }

    const int lane = threadIdx.x & 31;
    const int grp  = lane / 10;
    const int slot = lane - grp * 10;
    const bool act = lane < 30;

    float4 acc = make_float4(0.f, 0.f, 0.f, 0.f);
    if (act) {
        int e = grp;
        for (; e + 3 < cnt; e += 6) {
            int2 ea = __ldg(slots + e);
            int2 eb = __ldg(slots + e + 3);
            float4 ha = __ldg(reinterpret_cast<const float4*>(
                              G + (size_t)ea.x * OC + slot * 4));
            float4 hb = __ldg(reinterpret_cast<const float4*>(
                              G + (size_t)eb.x * OC + slot * 4));
            float va = __int_as_float(ea.y);
            float vb = __int_as_float(eb.y);
            acc.x += va * ha.x + vb * hb.x;
            acc.y += va * ha.y + vb * hb.y;
            acc.z += va * ha.z + vb * hb.z;
            acc.w += va * ha.w + vb * hb.w;
        }
        if (e < cnt) {
            int2 ea = __ldg(slots + e);
            float4 ha = __ldg(reinterpret_cast<const float4*>(
                              G + (size_t)ea.x * OC + slot * 4));
            float va = __int_as_float(ea.y);
            acc.x += va * ha.x; acc.y += va * ha.y;
            acc.z += va * ha.z; acc.w += va * ha.w;
        }
    }
    float4 b1, b2;
    b1.x = __shfl_down_sync(0xffffffffu, acc.x, 10);
    b1.y = __shfl_down_sync(0xffffffffu, acc.y, 10);
    b1.z = __shfl_down_sync(0xffffffffu, acc.z, 10);
    b1.w = __shfl_down_sync(0xffffffffu, acc.w, 10);
    b2.x = __shfl_down_sync(0xffffffffu, acc.x, 20);
    b2.y = __shfl_down_sync(0xffffffffu, acc.y, 20);
    b2.z = __shfl_down_sync(0xffffffffu, acc.z, 20);
    b2.w = __shfl_down_sync(0xffffffffu, acc.w, 20);

    if (lane < 10) {
        float* dst = out + (size_t)r * OC + slot * 4;
        float4 s = make_float4(acc.x + b1.x + b2.x, acc.y + b1.y + b2.y,
                               acc.z + b1.z + b2.z, acc.w + b1.w + b2.w);
        asm volatile("red.global.add.v4.f32 [%0], {%1,%2,%3,%4};"
                     :: "l"(dst), "f"(s.x), "f"(s.y), "f"(s.z), "f"(s.w)
                     : "memory");
    }
}

// ---------------------------------------------------------------------------
// FIXUP: process overflow edges (normally zero of them).
// ---------------------------------------------------------------------------
__global__ void fixup(float* __restrict__ out) {
    int n = g_ovf_n;
    if (n > OVFMAX) n = OVFMAX;
    for (int i = threadIdx.x; i < n; i += blockDim.x) {
        int4 e = g_ovf[i];
        const float* G = e.x ? g_g2 : g_g1;
        float v = __int_as_float(e.w);
        for (int j = 0; j < OC; j++) {
            float p = v * G[(size_t)e.z * OC + j];
            asm volatile("red.global.add.f32 [%0], %1;"
                         :: "l"(out + (size_t)e.y * OC + j), "f"(p) : "memory");
        }
    }
}

// ---------------------------------------------------------------------------
// Launch: fuse_w -> zero -> scatter -> biggemm -> gather -> fixup
// ---------------------------------------------------------------------------
extern "C" void kernel_launch(void* const* d_in, const int* in_sizes, int n_in,
                              void* d_out, int out_size) {
    const float* x   = (const float*)d_in[0];
    const int*   a1r = (const int*)  d_in[2];
    const int*   a1c = (const int*)  d_in[3];
    const float* a1v = (const float*)d_in[4];
    const int*   a2r = (const int*)  d_in[5];
    const int*   a2c = (const int*)  d_in[6];
    const float* a2v = (const float*)d_in[7];
    const float* w1  = (const float*)d_in[8];
    const float* w2  = (const float*)d_in[9];
    const float* b2  = (const float*)d_in[10];
    float* out = (float*)d_out;
    const int E1 = in_sizes[4];
    const int E2 = in_sizes[7];
    const int Et = E1 + E2;

    fuse_w<<<NC, 256>>>(w1, w2);
    zero_cnt<<<(2 * NN + 255) / 256, 256>>>();
    scatter<<<(Et + 255) / 256, 256>>>(a1r, a1c, a1v, E1, a2r, a2c, a2v, E2);

    biggemm<<<(NN + 127) / 128, 256>>>(x, b2, out);

    gather<<<(2 * NN * 32 + 255) / 256, 256>>>(out);
    fixup<<<1, 256>>>(out);
}

// round 11
// speedup vs baseline: 1.2514x; 1.1536x over previous
#include <cuda_runtime.h>
#include <stdint.h>

#define NN     100000
#define INC    256
#define HIDC   64
#define OC     40
#define MAXD1  64
#define MAXD2  80
#define OVFMAX 65536

static __device__ float g_h0[(size_t)NN * HIDC];
static __device__ float g_g1[(size_t)NN * OC];
static __device__ float g_g2[(size_t)NN * OC];
static __device__ __align__(16) float g_wt[64 * 128];  // [k][c] fc_out_w transposed
static __device__ int   g_cnt1[NN];
static __device__ int   g_cnt2[NN];
static __device__ int2  g_slot1[(size_t)NN * MAXD1];   // (col, val-bits)
static __device__ int2  g_slot2[(size_t)NN * MAXD2];
static __device__ int   g_ovf_n;
static __device__ int4  g_ovf[OVFMAX];                 // (graph, row, col, val-bits)

// ---------------- packed fp32 helpers (FFMA2 via PTX fma.rn.f32x2) ----------
__device__ __forceinline__ unsigned long long fma2(unsigned long long a,
                                                   unsigned long long b,
                                                   unsigned long long c) {
    unsigned long long d;
    asm("fma.rn.f32x2 %0, %1, %2, %3;" : "=l"(d) : "l"(a), "l"(b), "l"(c));
    return d;
}
__device__ __forceinline__ unsigned long long dup2(float x) {
    unsigned long long d;
    asm("mov.b64 %0, {%1, %1};" : "=l"(d) : "f"(x));
    return d;
}
__device__ __forceinline__ float2 unpk(unsigned long long v) {
    float2 r;
    asm("mov.b64 {%0, %1}, %2;" : "=f"(r.x), "=f"(r.y) : "l"(v));
    return r;
}

// ---------------------------------------------------------------------------
// WTRANS: g_wt[k*128+c] = fc_out_w[(c%40)][(c/40)*64 + k], c in [0,120); pad 0.
// One-time tiny kernel so proj2 can stage weights with coalesced float4.
// ---------------------------------------------------------------------------
__global__ void wtrans(const float* __restrict__ w) {
    int idx = blockIdx.x * blockDim.x + threadIdx.x;   // 0..8191
    if (idx >= 64 * 128) return;
    int k = idx >> 7;
    int c = idx & 127;
    float val = 0.f;
    if (c < 120) {
        int o = c % 40;
        int s = c / 40;
        val = w[o * 192 + s * 64 + k];
    }
    g_wt[idx] = val;
}

// ---------------------------------------------------------------------------
// GEMM1: h0 = x @ fc1_w^T    x[NN,256], w[64,256] -> g_h0[NN,64]
// (round-8 version: 128x64 tile, thread 8 rows x 4 cols, 94 us)
// ---------------------------------------------------------------------------
__global__ __launch_bounds__(256) void gemm1(const float* __restrict__ x,
                                             const float* __restrict__ w) {
    __shared__ __align__(16) float xs[128][36];
    __shared__ __align__(16) float ws_t[32][68];
    const int tid = threadIdx.x;
    const int tx = tid & 15;
    const int ty = tid >> 4;
    const int row0 = blockIdx.x * 128;

    unsigned long long acc0[8], acc1[8];
#pragma unroll
    for (int i = 0; i < 8; i++) { acc0[i] = 0ULL; acc1[i] = 0ULL; }

    for (int k0 = 0; k0 < INC; k0 += 32) {
#pragma unroll
        for (int q = 0; q < 4; q++) {
            int f  = tid + q * 256;
            int k4 = f & 7;
            int r  = f >> 3;
            int gr = min(row0 + r, NN - 1);
            float4 xv = *reinterpret_cast<const float4*>(x + (size_t)gr * INC + k0 + k4 * 4);
            *reinterpret_cast<float4*>(&xs[r][k4 * 4]) = xv;
        }
#pragma unroll
        for (int q = 0; q < 2; q++) {
            int f  = tid + q * 256;
            int k4 = f & 7;
            int n  = f >> 3;
            float4 wv = *reinterpret_cast<const float4*>(w + (size_t)n * INC + k0 + k4 * 4);
            ws_t[k4 * 4 + 0][n] = wv.x;
            ws_t[k4 * 4 + 1][n] = wv.y;
            ws_t[k4 * 4 + 2][n] = wv.z;
            ws_t[k4 * 4 + 3][n] = wv.w;
        }
        __syncthreads();
#pragma unroll 2
        for (int k4 = 0; k4 < 8; k4++) {
            ulonglong2 bb[4];
#pragma unroll
            for (int k = 0; k < 4; k++)
                bb[k] = *reinterpret_cast<const ulonglong2*>(&ws_t[k4 * 4 + k][tx * 4]);
#pragma unroll
            for (int i = 0; i < 8; i++) {
                float4 a4 = *reinterpret_cast<const float4*>(&xs[ty * 8 + i][k4 * 4]);
                unsigned long long aa;
                aa = dup2(a4.x); acc0[i] = fma2(aa, bb[0].x, acc0[i]); acc1[i] = fma2(aa, bb[0].y, acc1[i]);
                aa = dup2(a4.y); acc0[i] = fma2(aa, bb[1].x, acc0[i]); acc1[i] = fma2(aa, bb[1].y, acc1[i]);
                aa = dup2(a4.z); acc0[i] = fma2(aa, bb[2].x, acc0[i]); acc1[i] = fma2(aa, bb[2].y, acc1[i]);
                aa = dup2(a4.w); acc0[i] = fma2(aa, bb[3].x, acc0[i]); acc1[i] = fma2(aa, bb[3].y, acc1[i]);
            }
        }
        __syncthreads();
    }
#pragma unroll
    for (int i = 0; i < 8; i++) {
        int gr = row0 + ty * 8 + i;
        if (gr < NN) {
            float2 lo = unpk(acc0[i]);
            float2 hi = unpk(acc1[i]);
            *reinterpret_cast<float4*>(g_h0 + (size_t)gr * HIDC + tx * 4) =
                make_float4(lo.x, lo.y, hi.x, hi.y);
        }
    }
}

// ---------------------------------------------------------------------------
// PROJ2: register-tiled. Block = 128 rows x 128 cols (120 real),
// cols [0:40)=out(+bias), [40:80)=g1, [80:120)=g2, [120:128)=pad.
// Thread = 8x8. Weight staging now COALESCED float4 from pre-transposed g_wt.
// ---------------------------------------------------------------------------
__global__ __launch_bounds__(256) void proj2(const float* __restrict__ b,
                                             float* __restrict__ out) {
    __shared__ __align__(16) float hs[128][68];    // [row][k]
    __shared__ __align__(16) float wt[64][132];    // [k][col]
    __shared__ float bs[OC];
    const int tid = threadIdx.x;
    const int row0 = blockIdx.x * 128;

    // coalesced weight staging: 2048 float4 (64 k x 32 c4)
#pragma unroll
    for (int q = 0; q < 8; q++) {
        int f  = tid + q * 256;
        int k  = f >> 5;
        int c4 = f & 31;
        float4 wv = *reinterpret_cast<const float4*>(g_wt + k * 128 + c4 * 4);
        *reinterpret_cast<float4*>(&wt[k][c4 * 4]) = wv;
    }
    if (tid < OC) bs[tid] = b[tid];
    // h0 tile: 128 rows x 64 floats, coalesced float4
#pragma unroll
    for (int q = 0; q < 8; q++) {
        int f  = tid + q * 256;
        int k4 = f & 15;
        int r  = f >> 4;
        int gr = min(row0 + r, NN - 1);
        *reinterpret_cast<float4*>(&hs[r][k4 * 4]) =
            *reinterpret_cast<const float4*>(g_h0 + (size_t)gr * HIDC + k4 * 4);
    }
    __syncthreads();

    const int tx = tid & 15;       // cols tx*8 .. tx*8+7
    const int ty = tid >> 4;       // rows ty*8 .. ty*8+7

    unsigned long long acc[8][4];
#pragma unroll
    for (int i = 0; i < 8; i++)
#pragma unroll
        for (int j = 0; j < 4; j++) acc[i][j] = 0ULL;

#pragma unroll 2
    for (int k4 = 0; k4 < 16; k4++) {
        ulonglong2 bb[4][2];
#pragma unroll
        for (int k = 0; k < 4; k++) {
            bb[k][0] = *reinterpret_cast<const ulonglong2*>(&wt[k4 * 4 + k][tx * 8]);
            bb[k][1] = *reinterpret_cast<const ulonglong2*>(&wt[k4 * 4 + k][tx * 8 + 4]);
        }
#pragma unroll
        for (int i = 0; i < 8; i++) {
            float4 a4 = *reinterpret_cast<const float4*>(&hs[ty * 8 + i][k4 * 4]);
            unsigned long long aa;
            aa = dup2(a4.x);
            acc[i][0] = fma2(aa, bb[0][0].x, acc[i][0]);
            acc[i][1] = fma2(aa, bb[0][0].y, acc[i][1]);
            acc[i][2] = fma2(aa, bb[0][1].x, acc[i][2]);
            acc[i][3] = fma2(aa, bb[0][1].y, acc[i][3]);
            aa = dup2(a4.y);
            acc[i][0] = fma2(aa, bb[1][0].x, acc[i][0]);
            acc[i][1] = fma2(aa, bb[1][0].y, acc[i][1]);
            acc[i][2] = fma2(aa, bb[1][1].x, acc[i][2]);
            acc[i][3] = fma2(aa, bb[1][1].y, acc[i][3]);
            aa = dup2(a4.z);
            acc[i][0] = fma2(aa, bb[2][0].x, acc[i][0]);
            acc[i][1] = fma2(aa, bb[2][0].y, acc[i][1]);
            acc[i][2] = fma2(aa, bb[2][1].x, acc[i][2]);
            acc[i][3] = fma2(aa, bb[2][1].y, acc[i][3]);
            aa = dup2(a4.w);
            acc[i][0] = fma2(aa, bb[3][0].x, acc[i][0]);
            acc[i][1] = fma2(aa, bb[3][0].y, acc[i][1]);
            acc[i][2] = fma2(aa, bb[3][1].x, acc[i][2]);
            acc[i][3] = fma2(aa, bb[3][1].y, acc[i][3]);
        }
    }

    if (tx < 15) {                         // tx==15 = zero pad cols
        const int c0 = tx * 8;
        const int s  = c0 / 40;            // 8-col group never straddles a segment
        const int cb = c0 - s * 40;
        float* base = (s == 0) ? out : (s == 1) ? g_g1 : g_g2;
#pragma unroll
        for (int i = 0; i < 8; i++) {
            int gr = row0 + ty * 8 + i;
            if (gr < NN) {
                float2 p0 = unpk(acc[i][0]);
                float2 p1 = unpk(acc[i][1]);
                float2 p2 = unpk(acc[i][2]);
                float2 p3 = unpk(acc[i][3]);
                float4 v0 = make_float4(p0.x, p0.y, p1.x, p1.y);
                float4 v1 = make_float4(p2.x, p2.y, p3.x, p3.y);
                if (s == 0) {
                    v0.x += bs[cb + 0]; v0.y += bs[cb + 1];
                    v0.z += bs[cb + 2]; v0.w += bs[cb + 3];
                    v1.x += bs[cb + 4]; v1.y += bs[cb + 5];
                    v1.z += bs[cb + 6]; v1.w += bs[cb + 7];
                }
                *reinterpret_cast<float4*>(base + (size_t)gr * OC + cb)     = v0;
                *reinterpret_cast<float4*>(base + (size_t)gr * OC + cb + 4) = v1;
            }
        }
    }
}

// ---------------------------------------------------------------------------
// Binning: zero counters -> scatter edges into fixed-stride per-row bins.
// ---------------------------------------------------------------------------
__global__ void zero_cnt() {
    int i = blockIdx.x * blockDim.x + threadIdx.x;
    if (i < NN)          g_cnt1[i] = 0;
    else if (i < 2 * NN) g_cnt2[i - NN] = 0;
    if (i == 0) g_ovf_n = 0;
}

__global__ void scatter(const int* __restrict__ r1, const int* __restrict__ c1,
                        const float* __restrict__ v1, int E1,
                        const int* __restrict__ r2, const int* __restrict__ c2,
                        const float* __restrict__ v2, int E2) {
    int i = blockIdx.x * blockDim.x + threadIdx.x;
    if (i < E1) {
        int r = __ldg(r1 + i);
        int c = __ldg(c1 + i);
        int v = __float_as_int(__ldg(v1 + i));
        int p = atomicAdd(&g_cnt1[r], 1);
        if (p < MAXD1) {
            g_slot1[(size_t)r * MAXD1 + p] = make_int2(c, v);
        } else {
            int o = atomicAdd(&g_ovf_n, 1);
            if (o < OVFMAX) g_ovf[o] = make_int4(0, r, c, v);
        }
    } else if (i < E1 + E2) {
        int j = i - E1;
        int r = __ldg(r2 + j);
        int c = __ldg(c2 + j);
        int v = __float_as_int(__ldg(v2 + j));
        int p = atomicAdd(&g_cnt2[r], 1);
        if (p < MAXD2) {
            g_slot2[(size_t)r * MAXD2 + p] = make_int2(c, v);
        } else {
            int o = atomicAdd(&g_ovf_n, 1);
            if (o < OVFMAX) g_ovf[o] = make_int4(1, r, c, v);
        }
    }
}

// ---------------------------------------------------------------------------
// GATHER: 2 warps per row (one per graph). Warp: 3 edges x 10 float4-lanes,
// unroll-2. Capture-first 3-way shfl combine, then one 10-lane red.v4.
// ---------------------------------------------------------------------------
__global__ __launch_bounds__(256) void gather(float* __restrict__ out) {
    const int w = (int)((blockIdx.x * blockDim.x + threadIdx.x) >> 5);
    if (w >= 2 * NN) return;
    const int r = w >> 1;
    const int g = w & 1;

    const int2*  slots;
    const float* G;
    int cnt;
    if (g == 0) {
        slots = g_slot1 + (size_t)r * MAXD1;
        G     = g_g1;
        cnt   = min(__ldg(&g_cnt1[r]), MAXD1);
    } else {
        slots = g_slot2 + (size_t)r * MAXD2;
        G     = g_g2;
        cnt   = min(__ldg(&g_cnt2[r]), MAXD2);
    }

    const int lane = threadIdx.x & 31;
    const int grp  = lane / 10;
    const int slot = lane - grp * 10;
    const bool act = lane < 30;

    float4 acc = make_float4(0.f, 0.f, 0.f, 0.f);
    if (act) {
        int e = grp;
        for (; e + 3 < cnt; e += 6) {
            int2 ea = __ldg(slots + e);
            int2 eb = __ldg(slots + e + 3);
            float4 ha = __ldg(reinterpret_cast<const float4*>(
                              G + (size_t)ea.x * OC + slot * 4));
            float4 hb = __ldg(reinterpret_cast<const float4*>(
                              G + (size_t)eb.x * OC + slot * 4));
            float va = __int_as_float(ea.y);
            float vb = __int_as_float(eb.y);
            acc.x += va * ha.x + vb * hb.x;
            acc.y += va * ha.y + vb * hb.y;
            acc.z += va * ha.z + vb * hb.z;
            acc.w += va * ha.w + vb * hb.w;
        }
        if (e < cnt) {
            int2 ea = __ldg(slots + e);
            float4 ha = __ldg(reinterpret_cast<const float4*>(
                              G + (size_t)ea.x * OC + slot * 4));
            float va = __int_as_float(ea.y);
            acc.x += va * ha.x; acc.y += va * ha.y;
            acc.z += va * ha.z; acc.w += va * ha.w;
        }
    }
    float4 b1, b2;
    b1.x = __shfl_down_sync(0xffffffffu, acc.x, 10);
    b1.y = __shfl_down_sync(0xffffffffu, acc.y, 10);
    b1.z = __shfl_down_sync(0xffffffffu, acc.z, 10);
    b1.w = __shfl_down_sync(0xffffffffu, acc.w, 10);
    b2.x = __shfl_down_sync(0xffffffffu, acc.x, 20);
    b2.y = __shfl_down_sync(0xffffffffu, acc.y, 20);
    b2.z = __shfl_down_sync(0xffffffffu, acc.z, 20);
    b2.w = __shfl_down_sync(0xffffffffu, acc.w, 20);

    if (lane < 10) {
        float* dst = out + (size_t)r * OC + slot * 4;
        float4 s = make_float4(acc.x + b1.x + b2.x, acc.y + b1.y + b2.y,
                               acc.z + b1.z + b2.z, acc.w + b1.w + b2.w);
        asm volatile("red.global.add.v4.f32 [%0], {%1,%2,%3,%4};"
                     :: "l"(dst), "f"(s.x), "f"(s.y), "f"(s.z), "f"(s.w)
                     : "memory");
    }
}

// ---------------------------------------------------------------------------
// FIXUP: process overflow edges (normally zero of them).
// ---------------------------------------------------------------------------
__global__ void fixup(float* __restrict__ out) {
    int n = g_ovf_n;
    if (n > OVFMAX) n = OVFMAX;
    for (int i = threadIdx.x; i < n; i += blockDim.x) {
        int4 e = g_ovf[i];
        const float* G = e.x ? g_g2 : g_g1;
        float v = __int_as_float(e.w);
        for (int j = 0; j < OC; j++) {
            float p = v * G[(size_t)e.z * OC + j];
            asm volatile("red.global.add.f32 [%0], %1;"
                         :: "l"(out + (size_t)e.y * OC + j), "f"(p) : "memory");
        }
    }
}

// ---------------------------------------------------------------------------
// Launch with capture fork: [zero+scatter] || [wtrans+gemm1+proj2]; join; gather.
// ---------------------------------------------------------------------------
extern "C" void kernel_launch(void* const* d_in, const int* in_sizes, int n_in,
                              void* d_out, int out_size) {
    const float* x   = (const float*)d_in[0];
    const int*   a1r = (const int*)  d_in[2];
    const int*   a1c = (const int*)  d_in[3];
    const float* a1v = (const float*)d_in[4];
    const int*   a2r = (const int*)  d_in[5];
    const int*   a2c = (const int*)  d_in[6];
    const float* a2v = (const float*)d_in[7];
    const float* w1  = (const float*)d_in[8];
    const float* w2  = (const float*)d_in[9];
    const float* b2  = (const float*)d_in[10];
    float* out = (float*)d_out;
    const int E1 = in_sizes[4];
    const int E2 = in_sizes[7];
    const int Et = E1 + E2;

    cudaStream_t s2;
    cudaEvent_t  e0, e1;
    cudaStreamCreateWithFlags(&s2, cudaStreamNonBlocking);
    cudaEventCreateWithFlags(&e0, cudaEventDisableTiming);
    cudaEventCreateWithFlags(&e1, cudaEventDisableTiming);

    cudaEventRecord(e0, 0);
    cudaStreamWaitEvent(s2, e0, 0);
    zero_cnt<<<(2 * NN + 255) / 256, 256, 0, s2>>>();
    scatter<<<(Et + 255) / 256, 256, 0, s2>>>(a1r, a1c, a1v, E1,
                                              a2r, a2c, a2v, E2);
    cudaEventRecord(e1, s2);

    wtrans<<<32, 256>>>(w2);
    gemm1<<<(NN + 127) / 128, 256>>>(x, w1);
    proj2<<<(NN + 127) / 128, 256>>>(b2, out);

    cudaStreamWaitEvent(0, e1, 0);
    gather<<<(2 * NN * 32 + 255) / 256, 256>>>(out);
    fixup<<<1, 256>>>(out);

    cudaStreamDestroy(s2);
    cudaEventDestroy(e0);
    cudaEventDestroy(e1);
}

// round 13
// speedup vs baseline: 1.3698x; 1.0946x over previous
#include <cuda_runtime.h>
#include <stdint.h>

#define NN     100000
#define INC    256
#define HIDC   64
#define OC     40
#define MAXD1  64
#define MAXD2  80
#define OVFMAX 65536

static __device__ float g_h0[(size_t)NN * HIDC];
static __device__ float g_g1[(size_t)NN * OC];
static __device__ float g_g2[(size_t)NN * OC];
static __device__ __align__(16) float g_wt[64 * 128];  // [k][c] fc_out_w transposed
static __device__ int   g_cnt1[NN];
static __device__ int   g_cnt2[NN];
static __device__ int2  g_slot1[(size_t)NN * MAXD1];   // (col, val-bits)
static __device__ int2  g_slot2[(size_t)NN * MAXD2];
static __device__ int   g_ovf_n;
static __device__ int4  g_ovf[OVFMAX];                 // (graph, row, col, val-bits)

// ---------------- packed fp32 helpers (FFMA2 via PTX fma.rn.f32x2) ----------
__device__ __forceinline__ unsigned long long fma2(unsigned long long a,
                                                   unsigned long long b,
                                                   unsigned long long c) {
    unsigned long long d;
    asm("fma.rn.f32x2 %0, %1, %2, %3;" : "=l"(d) : "l"(a), "l"(b), "l"(c));
    return d;
}
__device__ __forceinline__ unsigned long long dup2(float x) {
    unsigned long long d;
    asm("mov.b64 %0, {%1, %1};" : "=l"(d) : "f"(x));
    return d;
}
__device__ __forceinline__ float2 unpk(unsigned long long v) {
    float2 r;
    asm("mov.b64 {%0, %1}, %2;" : "=f"(r.x), "=f"(r.y) : "l"(v));
    return r;
}
__device__ __forceinline__ uint32_t to_tf32(float f) {
    uint32_t r;
    asm("cvt.rna.tf32.f32 %0, %1;" : "=r"(r) : "f"(f));
    return r;
}

// ---------------------------------------------------------------------------
// GEMM1_MMA: h0 = x @ fc1_w^T via warp-level mma.sync tf32 (HMMA, sm_80+ path).
// Block 256 thr = 8 warps (4 m x 2 n). Block tile 128x64; warp tile 32x32
// (2 m16-tiles x 4 n8-tiles). K-chunk 32, inputs pre-rounded with cvt.rna.tf32.
// ---------------------------------------------------------------------------
__global__ __launch_bounds__(256) void gemm1_mma(const float* __restrict__ x,
                                                 const float* __restrict__ w) {
    __shared__ __align__(16) uint32_t xs[128][36];   // [row][k], tf32 bits
    __shared__ __align__(16) uint32_t ws[64][36];    // [n][k],  tf32 bits
    const int tid  = threadIdx.x;
    const int wid  = tid >> 5;
    const int lane = tid & 31;
    const int wm   = wid & 3;          // m-group: rows wm*32..wm*32+31
    const int wn   = wid >> 2;         // n-group: cols wn*32..wn*32+31
    const int grp  = lane >> 2;        // 0..7
    const int tig  = lane & 3;         // 0..3
    const int row0 = blockIdx.x * 128;

    float c[2][4][4];
#pragma unroll
    for (int mt = 0; mt < 2; mt++)
#pragma unroll
        for (int nt = 0; nt < 4; nt++)
#pragma unroll
            for (int j = 0; j < 4; j++) c[mt][nt][j] = 0.f;

    for (int k0 = 0; k0 < INC; k0 += 32) {
        // stage x tile: 128 rows x 32 k (1024 float4)
#pragma unroll
        for (int q = 0; q < 4; q++) {
            int f  = tid + q * 256;
            int k4 = f & 7;
            int r  = f >> 3;
            int gr = min(row0 + r, NN - 1);
            float4 v = __ldg(reinterpret_cast<const float4*>(x + (size_t)gr * INC + k0 + k4 * 4));
            uint4 t = make_uint4(to_tf32(v.x), to_tf32(v.y), to_tf32(v.z), to_tf32(v.w));
            *reinterpret_cast<uint4*>(&xs[r][k4 * 4]) = t;
        }
        // stage w tile: 64 rows x 32 k (512 float4)
#pragma unroll
        for (int q = 0; q < 2; q++) {
            int f  = tid + q * 256;
            int k4 = f & 7;
            int n  = f >> 3;
            float4 v = __ldg(reinterpret_cast<const float4*>(w + (size_t)n * INC + k0 + k4 * 4));
            uint4 t = make_uint4(to_tf32(v.x), to_tf32(v.y), to_tf32(v.z), to_tf32(v.w));
            *reinterpret_cast<uint4*>(&ws[n][k4 * 4]) = t;
        }
        __syncthreads();

#pragma unroll
        for (int s = 0; s < 4; s++) {        // k8-steps within chunk
            const int kk = s * 8;
            uint32_t a[2][4], b[4][2];
#pragma unroll
            for (int mt = 0; mt < 2; mt++) {
                int m = wm * 32 + mt * 16;
                a[mt][0] = xs[m + grp][kk + tig];
                a[mt][1] = xs[m + 8 + grp][kk + tig];
                a[mt][2] = xs[m + grp][kk + tig + 4];
                a[mt][3] = xs[m + 8 + grp][kk + tig + 4];
            }
#pragma unroll
            for (int nt = 0; nt < 4; nt++) {
                int n = wn * 32 + nt * 8;
                b[nt][0] = ws[n + grp][kk + tig];
                b[nt][1] = ws[n + grp][kk + tig + 4];
            }
#pragma unroll
            for (int mt = 0; mt < 2; mt++)
#pragma unroll
                for (int nt = 0; nt < 4; nt++) {
                    asm volatile(
                        "mma.sync.aligned.m16n8k8.row.col.f32.tf32.tf32.f32 "
                        "{%0,%1,%2,%3}, {%4,%5,%6,%7}, {%8,%9}, {%0,%1,%2,%3};"
                        : "+f"(c[mt][nt][0]), "+f"(c[mt][nt][1]),
                          "+f"(c[mt][nt][2]), "+f"(c[mt][nt][3])
                        : "r"(a[mt][0]), "r"(a[mt][1]), "r"(a[mt][2]), "r"(a[mt][3]),
                          "r"(b[nt][0]), "r"(b[nt][1]));
                }
        }
        __syncthreads();
    }

    // epilogue: c frag (m16n8): c0/c1 at (grp, 2*tig[+1]); c2/c3 at (grp+8, ...)
#pragma unroll
    for (int mt = 0; mt < 2; mt++) {
        int r_lo = row0 + wm * 32 + mt * 16 + grp;
        int r_hi = r_lo + 8;
#pragma unroll
        for (int nt = 0; nt < 4; nt++) {
            int col = wn * 32 + nt * 8 + 2 * tig;
            if (r_lo < NN)
                *reinterpret_cast<float2*>(g_h0 + (size_t)r_lo * HIDC + col) =
                    make_float2(c[mt][nt][0], c[mt][nt][1]);
            if (r_hi < NN)
                *reinterpret_cast<float2*>(g_h0 + (size_t)r_hi * HIDC + col) =
                    make_float2(c[mt][nt][2], c[mt][nt][3]);
        }
    }
}

// ---------------------------------------------------------------------------
// WTRANS: g_wt[k*128+c] = fc_out_w[(c%40)][(c/40)*64 + k], c in [0,120); pad 0.
// ---------------------------------------------------------------------------
__global__ void wtrans(const float* __restrict__ w) {
    int idx = blockIdx.x * blockDim.x + threadIdx.x;   // 0..8191
    if (idx >= 64 * 128) return;
    int k = idx >> 7;
    int c = idx & 127;
    float val = 0.f;
    if (c < 120) {
        int o = c % 40;
        int s = c / 40;
        val = w[o * 192 + s * 64 + k];
    }
    g_wt[idx] = val;
}

// ---------------------------------------------------------------------------
// PROJ2: register-tiled fp32. Block = 128 rows x 128 cols (120 real), thread 8x8.
// ---------------------------------------------------------------------------
__global__ __launch_bounds__(256) void proj2(const float* __restrict__ b,
                                             float* __restrict__ out) {
    __shared__ __align__(16) float hs[128][68];    // [row][k]
    __shared__ __align__(16) float wt[64][132];    // [k][col]
    __shared__ float bs[OC];
    const int tid = threadIdx.x;
    const int row0 = blockIdx.x * 128;

#pragma unroll
    for (int q = 0; q < 8; q++) {
        int f  = tid + q * 256;
        int k  = f >> 5;
        int c4 = f & 31;
        float4 wv = *reinterpret_cast<const float4*>(g_wt + k * 128 + c4 * 4);
        *reinterpret_cast<float4*>(&wt[k][c4 * 4]) = wv;
    }
    if (tid < OC) bs[tid] = b[tid];
#pragma unroll
    for (int q = 0; q < 8; q++) {
        int f  = tid + q * 256;
        int k4 = f & 15;
        int r  = f >> 4;
        int gr = min(row0 + r, NN - 1);
        *reinterpret_cast<float4*>(&hs[r][k4 * 4]) =
            *reinterpret_cast<const float4*>(g_h0 + (size_t)gr * HIDC + k4 * 4);
    }
    __syncthreads();

    const int tx = tid & 15;
    const int ty = tid >> 4;

    unsigned long long acc[8][4];
#pragma unroll
    for (int i = 0; i < 8; i++)
#pragma unroll
        for (int j = 0; j < 4; j++) acc[i][j] = 0ULL;

#pragma unroll 2
    for (int k4 = 0; k4 < 16; k4++) {
        ulonglong2 bb[4][2];
#pragma unroll
        for (int k = 0; k < 4; k++) {
            bb[k][0] = *reinterpret_cast<const ulonglong2*>(&wt[k4 * 4 + k][tx * 8]);
            bb[k][1] = *reinterpret_cast<const ulonglong2*>(&wt[k4 * 4 + k][tx * 8 + 4]);
        }
#pragma unroll
        for (int i = 0; i < 8; i++) {
            float4 a4 = *reinterpret_cast<const float4*>(&hs[ty * 8 + i][k4 * 4]);
            unsigned long long aa;
            aa = dup2(a4.x);
            acc[i][0] = fma2(aa, bb[0][0].x, acc[i][0]);
            acc[i][1] = fma2(aa, bb[0][0].y, acc[i][1]);
            acc[i][2] = fma2(aa, bb[0][1].x, acc[i][2]);
            acc[i][3] = fma2(aa, bb[0][1].y, acc[i][3]);
            aa = dup2(a4.y);
            acc[i][0] = fma2(aa, bb[1][0].x, acc[i][0]);
            acc[i][1] = fma2(aa, bb[1][0].y, acc[i][1]);
            acc[i][2] = fma2(aa, bb[1][1].x, acc[i][2]);
            acc[i][3] = fma2(aa, bb[1][1].y, acc[i][3]);
            aa = dup2(a4.z);
            acc[i][0] = fma2(aa, bb[2][0].x, acc[i][0]);
            acc[i][1] = fma2(aa, bb[2][0].y, acc[i][1]);
            acc[i][2] = fma2(aa, bb[2][1].x, acc[i][2]);
            acc[i][3] = fma2(aa, bb[2][1].y, acc[i][3]);
            aa = dup2(a4.w);
            acc[i][0] = fma2(aa, bb[3][0].x, acc[i][0]);
            acc[i][1] = fma2(aa, bb[3][0].y, acc[i][1]);
            acc[i][2] = fma2(aa, bb[3][1].x, acc[i][2]);
            acc[i][3] = fma2(aa, bb[3][1].y, acc[i][3]);
        }
    }

    if (tx < 15) {
        const int c0 = tx * 8;
        const int s  = c0 / 40;
        const int cb = c0 - s * 40;
        float* base = (s == 0) ? out : (s == 1) ? g_g1 : g_g2;
#pragma unroll
        for (int i = 0; i < 8; i++) {
            int gr = row0 + ty * 8 + i;
            if (gr < NN) {
                float2 p0 = unpk(acc[i][0]);
                float2 p1 = unpk(acc[i][1]);
                float2 p2 = unpk(acc[i][2]);
                float2 p3 = unpk(acc[i][3]);
                float4 v0 = make_float4(p0.x, p0.y, p1.x, p1.y);
                float4 v1 = make_float4(p2.x, p2.y, p3.x, p3.y);
                if (s == 0) {
                    v0.x += bs[cb + 0]; v0.y += bs[cb + 1];
                    v0.z += bs[cb + 2]; v0.w += bs[cb + 3];
                    v1.x += bs[cb + 4]; v1.y += bs[cb + 5];
                    v1.z += bs[cb + 6]; v1.w += bs[cb + 7];
                }
                *reinterpret_cast<float4*>(base + (size_t)gr * OC + cb)     = v0;
                *reinterpret_cast<float4*>(base + (size_t)gr * OC + cb + 4) = v1;
            }
        }
    }
}

// ---------------------------------------------------------------------------
// Binning: zero counters -> scatter (4 edges/thread, vectorized loads).
// ---------------------------------------------------------------------------
__global__ void zero_cnt() {
    int i = blockIdx.x * blockDim.x + threadIdx.x;
    if (i < NN)          g_cnt1[i] = 0;
    else if (i < 2 * NN) g_cnt2[i - NN] = 0;
    if (i == 0) g_ovf_n = 0;
}

__device__ __forceinline__ void scat1(int r, int c, float vf, int2* slots,
                                      int* cnt, int maxd, int gflag) {
    int v = __float_as_int(vf);
    int p = atomicAdd(&cnt[r], 1);
    if (p < maxd) {
        slots[(size_t)r * maxd + p] = make_int2(c, v);
    } else {
        int o = atomicAdd(&g_ovf_n, 1);
        if (o < OVFMAX) g_ovf[o] = make_int4(gflag, r, c, v);
    }
}

__global__ void scatter(const int* __restrict__ r1, const int* __restrict__ c1,
                        const float* __restrict__ v1, int E1,
                        const int* __restrict__ r2, const int* __restrict__ c2,
                        const float* __restrict__ v2, int E2) {
    int t = blockIdx.x * blockDim.x + threadIdx.x;
    int q1 = (E1 + 3) >> 2;
    int q2 = (E2 + 3) >> 2;
    const int* R; const int* C; const float* V;
    int2* slots; int* cnt; int maxd, gflag, E, base;
    if (t < q1) {
        R = r1; C = c1; V = v1; E = E1; base = t * 4;
        slots = g_slot1; cnt = g_cnt1; maxd = MAXD1; gflag = 0;
    } else if (t < q1 + q2) {
        R = r2; C = c2; V = v2; E = E2; base = (t - q1) * 4;
        slots = g_slot2; cnt = g_cnt2; maxd = MAXD2; gflag = 1;
    } else return;

    if (base + 4 <= E) {
        int4   rr = __ldg(reinterpret_cast<const int4*>(R + base));
        int4   cc = __ldg(reinterpret_cast<const int4*>(C + base));
        float4 vv = __ldg(reinterpret_cast<const float4*>(V + base));
        scat1(rr.x, cc.x, vv.x, slots, cnt, maxd, gflag);
        scat1(rr.y, cc.y, vv.y, slots, cnt, maxd, gflag);
        scat1(rr.z, cc.z, vv.z, slots, cnt, maxd, gflag);
        scat1(rr.w, cc.w, vv.w, slots, cnt, maxd, gflag);
    } else {
        for (int j = base; j < E; j++)
            scat1(__ldg(R + j), __ldg(C + j), __ldg(V + j), slots, cnt, maxd, gflag);
    }
}

// ---------------------------------------------------------------------------
// GATHER: 2 warps per row (one per graph). Warp: 3 edges x 10 float4-lanes,
// unroll-2. Capture-first 3-way shfl combine, then one 10-lane red.v4.
// ---------------------------------------------------------------------------
__global__ __launch_bounds__(256) void gather(float* __restrict__ out) {
    const int w = (int)((blockIdx.x * blockDim.x + threadIdx.x) >> 5);
    if (w >= 2 * NN) return;
    const int r = w >> 1;
    const int g = w & 1;

    const int2*  slots;
    const float* G;
    int cnt;
    if (g == 0) {
        slots = g_slot1 + (size_t)r * MAXD1;
        G     = g_g1;
        cnt   = min(__ldg(&g_cnt1[r]), MAXD1);
    } else {
        slots = g_slot2 + (size_t)r * MAXD2;
        G     = g_g2;
        cnt   = min(__ldg(&g_cnt2[r]), MAXD2);
    }

    const int lane = threadIdx.x & 31;
    const int grp  = lane / 10;
    const int slot = lane - grp * 10;
    const bool act = lane < 30;

    float4 acc = make_float4(0.f, 0.f, 0.f, 0.f);
    if (act) {
        int e = grp;
        for (; e + 3 < cnt; e += 6) {
            int2 ea = __ldg(slots + e);
            int2 eb = __ldg(slots + e + 3);
            float4 ha = __ldg(reinterpret_cast<const float4*>(
                              G + (size_t)ea.x * OC + slot * 4));
            float4 hb = __ldg(reinterpret_cast<const float4*>(
                              G + (size_t)eb.x * OC + slot * 4));
            float va = __int_as_float(ea.y);
            float vb = __int_as_float(eb.y);
            acc.x += va * ha.x + vb * hb.x;
            acc.y += va * ha.y + vb * hb.y;
            acc.z += va * ha.z + vb * hb.z;
            acc.w += va * ha.w + vb * hb.w;
        }
        if (e < cnt) {
            int2 ea = __ldg(slots + e);
            float4 ha = __ldg(reinterpret_cast<const float4*>(
                              G + (size_t)ea.x * OC + slot * 4));
            float va = __int_as_float(ea.y);
            acc.x += va * ha.x; acc.y += va * ha.y;
            acc.z += va * ha.z; acc.w += va * ha.w;
        }
    }
    float4 b1, b2;
    b1.x = __shfl_down_sync(0xffffffffu, acc.x, 10);
    b1.y = __shfl_down_sync(0xffffffffu, acc.y, 10);
    b1.z = __shfl_down_sync(0xffffffffu, acc.z, 10);
    b1.w = __shfl_down_sync(0xffffffffu, acc.w, 10);
    b2.x = __shfl_down_sync(0xffffffffu, acc.x, 20);
    b2.y = __shfl_down_sync(0xffffffffu, acc.y, 20);
    b2.z = __shfl_down_sync(0xffffffffu, acc.z, 20);
    b2.w = __shfl_down_sync(0xffffffffu, acc.w, 20);

    if (lane < 10) {
        float* dst = out + (size_t)r * OC + slot * 4;
        float4 s = make_float4(acc.x + b1.x + b2.x, acc.y + b1.y + b2.y,
                               acc.z + b1.z + b2.z, acc.w + b1.w + b2.w);
        asm volatile("red.global.add.v4.f32 [%0], {%1,%2,%3,%4};"
                     :: "l"(dst), "f"(s.x), "f"(s.y), "f"(s.z), "f"(s.w)
                     : "memory");
    }
}

// ---------------------------------------------------------------------------
// FIXUP: process overflow edges (normally zero of them).
// ---------------------------------------------------------------------------
__global__ void fixup(float* __restrict__ out) {
    int n = g_ovf_n;
    if (n > OVFMAX) n = OVFMAX;
    for (int i = threadIdx.x; i < n; i += blockDim.x) {
        int4 e = g_ovf[i];
        const float* G = e.x ? g_g2 : g_g1;
        float v = __int_as_float(e.w);
        for (int j = 0; j < OC; j++) {
            float p = v * G[(size_t)e.z * OC + j];
            asm volatile("red.global.add.f32 [%0], %1;"
                         :: "l"(out + (size_t)e.y * OC + j), "f"(p) : "memory");
        }
    }
}

// ---------------------------------------------------------------------------
// Launch (serial): wtrans -> zero -> scatter -> gemm1_mma -> proj2 -> gather -> fixup
// ---------------------------------------------------------------------------
extern "C" void kernel_launch(void* const* d_in, const int* in_sizes, int n_in,
                              void* d_out, int out_size) {
    const float* x   = (const float*)d_in[0];
    const int*   a1r = (const int*)  d_in[2];
    const int*   a1c = (const int*)  d_in[3];
    const float* a1v = (const float*)d_in[4];
    const int*   a2r = (const int*)  d_in[5];
    const int*   a2c = (const int*)  d_in[6];
    const float* a2v = (const float*)d_in[7];
    const float* w1  = (const float*)d_in[8];
    const float* w2  = (const float*)d_in[9];
    const float* b2  = (const float*)d_in[10];
    float* out = (float*)d_out;
    const int E1 = in_sizes[4];
    const int E2 = in_sizes[7];

    wtrans<<<32, 256>>>(w2);
    zero_cnt<<<(2 * NN + 255) / 256, 256>>>();
    {
        int q = ((E1 + 3) >> 2) + ((E2 + 3) >> 2);
        scatter<<<(q + 255) / 256, 256>>>(a1r, a1c, a1v, E1, a2r, a2c, a2v, E2);
    }
    gemm1_mma<<<(NN + 127) / 128, 256>>>(x, w1);
    proj2<<<(NN + 127) / 128, 256>>>(b2, out);
    gather<<<(2 * NN * 32 + 255) / 256, 256>>>(out);
    fixup<<<1, 256>>>(out);
}

// round 14
// speedup vs baseline: 1.7112x; 1.2492x over previous
#include <cuda_runtime.h>
#include <stdint.h>

#define NN     100000
#define INC    256
#define HIDC   64
#define OC     40
#define MAXD1  64
#define MAXD2  80
#define OVFMAX 65536

static __device__ float g_g1[(size_t)NN * OC];
static __device__ float g_g2[(size_t)NN * OC];
static __device__ int   g_cnt1[NN];
static __device__ int   g_cnt2[NN];
static __device__ int2  g_slot1[(size_t)NN * MAXD1];   // (col, val-bits)
static __device__ int2  g_slot2[(size_t)NN * MAXD2];
static __device__ int   g_ovf_n;
static __device__ int4  g_ovf[OVFMAX];                 // (graph, row, col, val-bits)

__device__ __forceinline__ uint32_t to_tf32(float f) {
    uint32_t r;
    asm("cvt.rna.tf32.f32 %0, %1;" : "=r"(r) : "f"(f));
    return r;
}

// Dynamic smem layout (uint32 indices):
//   WB  [128][68] at 0        (fc_out_w as [c][k] tf32, pad cols >=120 zero)
//   XS  [128][36] at 8704     (phase 1 x tile)
//   WS  [64][36]  at 13312    (phase 1 w tile)
//   H0S [128][68] at 8704     (phase 2: overlays XS/WS)
#define OFF_WB  0
#define OFF_XS  8704
#define OFF_WS  13312
#define OFF_H0S 8704
#define SMEM_UINTS 17408
#define SMEM_BYTES (SMEM_UINTS * 4)

// ---------------------------------------------------------------------------
// FUSED: x[128,256] -(MMA1 tf32)-> h0[128,64] (smem, tf32)
//        -(MMA2 tf32)-> [out | g1 | g2][128,120] (+bias on out)
// Block 256 thr = 8 warps. MMA1: warps (wm 0..3) x (wn 0..1), warp tile 32x32.
// MMA2: warps (wm 0..3) x (wn2 0..1), warp tile 32x64.
// ---------------------------------------------------------------------------
__global__ __launch_bounds__(256) void fused_gemm(const float* __restrict__ x,
                                                  const float* __restrict__ w1,
                                                  const float* __restrict__ w2,
                                                  const float* __restrict__ bias,
                                                  float* __restrict__ out) {
    extern __shared__ uint32_t sm[];
    uint32_t* WB  = sm + OFF_WB;
    uint32_t* XS  = sm + OFF_XS;
    uint32_t* WS  = sm + OFF_WS;
    uint32_t* H0S = sm + OFF_H0S;

    const int tid  = threadIdx.x;
    const int wid  = tid >> 5;
    const int lane = tid & 31;
    const int wm   = wid & 3;          // m-group: rows wm*32..wm*32+31
    const int wn   = wid >> 2;         // phase-1 n-group (32 cols); phase-2 (64 cols)
    const int grp  = lane >> 2;        // 0..7
    const int tig  = lane & 3;         // 0..3
    const int row0 = blockIdx.x * 128;

    // stage WB: [c][k] tf32 from fc_out_w; c<120 real, else 0.  128 c x 16 float4
#pragma unroll
    for (int q = 0; q < 8; q++) {
        int f  = tid + q * 256;
        int c  = f >> 4;
        int k4 = f & 15;
        uint4 t = make_uint4(0u, 0u, 0u, 0u);
        if (c < 120) {
            int o = c % 40;
            int s = c / 40;
            float4 v = __ldg(reinterpret_cast<const float4*>(
                w2 + (size_t)o * 192 + s * 64 + k4 * 4));
            t = make_uint4(to_tf32(v.x), to_tf32(v.y), to_tf32(v.z), to_tf32(v.w));
        }
        *reinterpret_cast<uint4*>(&WB[c * 68 + k4 * 4]) = t;
    }

    // -------------------- phase 1: h0 = x @ w1^T --------------------
    float c1[2][4][4];
#pragma unroll
    for (int mt = 0; mt < 2; mt++)
#pragma unroll
        for (int nt = 0; nt < 4; nt++)
#pragma unroll
            for (int j = 0; j < 4; j++) c1[mt][nt][j] = 0.f;

    for (int k0 = 0; k0 < INC; k0 += 32) {
#pragma unroll
        for (int q = 0; q < 4; q++) {
            int f  = tid + q * 256;
            int k4 = f & 7;
            int r  = f >> 3;
            int gr = min(row0 + r, NN - 1);
            float4 v = __ldg(reinterpret_cast<const float4*>(x + (size_t)gr * INC + k0 + k4 * 4));
            uint4 t = make_uint4(to_tf32(v.x), to_tf32(v.y), to_tf32(v.z), to_tf32(v.w));
            *reinterpret_cast<uint4*>(&XS[r * 36 + k4 * 4]) = t;
        }
#pragma unroll
        for (int q = 0; q < 2; q++) {
            int f  = tid + q * 256;
            int k4 = f & 7;
            int n  = f >> 3;
            float4 v = __ldg(reinterpret_cast<const float4*>(w1 + (size_t)n * INC + k0 + k4 * 4));
            uint4 t = make_uint4(to_tf32(v.x), to_tf32(v.y), to_tf32(v.z), to_tf32(v.w));
            *reinterpret_cast<uint4*>(&WS[n * 36 + k4 * 4]) = t;
        }
        __syncthreads();

#pragma unroll
        for (int s = 0; s < 4; s++) {
            const int kk = s * 8;
            uint32_t a[2][4], b[4][2];
#pragma unroll
            for (int mt = 0; mt < 2; mt++) {
                int m = wm * 32 + mt * 16;
                a[mt][0] = XS[(m + grp) * 36 + kk + tig];
                a[mt][1] = XS[(m + 8 + grp) * 36 + kk + tig];
                a[mt][2] = XS[(m + grp) * 36 + kk + tig + 4];
                a[mt][3] = XS[(m + 8 + grp) * 36 + kk + tig + 4];
            }
#pragma unroll
            for (int nt = 0; nt < 4; nt++) {
                int n = wn * 32 + nt * 8;
                b[nt][0] = WS[(n + grp) * 36 + kk + tig];
                b[nt][1] = WS[(n + grp) * 36 + kk + tig + 4];
            }
#pragma unroll
            for (int mt = 0; mt < 2; mt++)
#pragma unroll
                for (int nt = 0; nt < 4; nt++) {
                    asm volatile(
                        "mma.sync.aligned.m16n8k8.row.col.f32.tf32.tf32.f32 "
                        "{%0,%1,%2,%3}, {%4,%5,%6,%7}, {%8,%9}, {%0,%1,%2,%3};"
                        : "+f"(c1[mt][nt][0]), "+f"(c1[mt][nt][1]),
                          "+f"(c1[mt][nt][2]), "+f"(c1[mt][nt][3])
                        : "r"(a[mt][0]), "r"(a[mt][1]), "r"(a[mt][2]), "r"(a[mt][3]),
                          "r"(b[nt][0]), "r"(b[nt][1]));
                }
        }
        __syncthreads();
    }

    // -------------------- h0 frags -> H0S (tf32) --------------------
#pragma unroll
    for (int mt = 0; mt < 2; mt++) {
        int r_lo = wm * 32 + mt * 16 + grp;
        int r_hi = r_lo + 8;
#pragma unroll
        for (int nt = 0; nt < 4; nt++) {
            int col = wn * 32 + nt * 8 + 2 * tig;
            *reinterpret_cast<uint2*>(&H0S[r_lo * 68 + col]) =
                make_uint2(to_tf32(c1[mt][nt][0]), to_tf32(c1[mt][nt][1]));
            *reinterpret_cast<uint2*>(&H0S[r_hi * 68 + col]) =
                make_uint2(to_tf32(c1[mt][nt][2]), to_tf32(c1[mt][nt][3]));
        }
    }
    __syncthreads();

    // -------------------- phase 2: [out|g1|g2] = h0 @ WB^T --------------------
    float c2[2][8][4];
#pragma unroll
    for (int mt = 0; mt < 2; mt++)
#pragma unroll
        for (int nt = 0; nt < 8; nt++)
#pragma unroll
            for (int j = 0; j < 4; j++) c2[mt][nt][j] = 0.f;

#pragma unroll
    for (int s = 0; s < 8; s++) {          // K=64, 8 k8-steps
        const int kk = s * 8;
        uint32_t a[2][4], b[8][2];
#pragma unroll
        for (int mt = 0; mt < 2; mt++) {
            int m = wm * 32 + mt * 16;
            a[mt][0] = H0S[(m + grp) * 68 + kk + tig];
            a[mt][1] = H0S[(m + 8 + grp) * 68 + kk + tig];
            a[mt][2] = H0S[(m + grp) * 68 + kk + tig + 4];
            a[mt][3] = H0S[(m + 8 + grp) * 68 + kk + tig + 4];
        }
#pragma unroll
        for (int nt = 0; nt < 8; nt++) {
            int n = wn * 64 + nt * 8;
            b[nt][0] = WB[(n + grp) * 68 + kk + tig];
            b[nt][1] = WB[(n + grp) * 68 + kk + tig + 4];
        }
#pragma unroll
        for (int mt = 0; mt < 2; mt++)
#pragma unroll
            for (int nt = 0; nt < 8; nt++) {
                asm volatile(
                    "mma.sync.aligned.m16n8k8.row.col.f32.tf32.tf32.f32 "
                    "{%0,%1,%2,%3}, {%4,%5,%6,%7}, {%8,%9}, {%0,%1,%2,%3};"
                    : "+f"(c2[mt][nt][0]), "+f"(c2[mt][nt][1]),
                      "+f"(c2[mt][nt][2]), "+f"(c2[mt][nt][3])
                    : "r"(a[mt][0]), "r"(a[mt][1]), "r"(a[mt][2]), "r"(a[mt][3]),
                      "r"(b[nt][0]), "r"(b[nt][1]));
            }
    }

    // -------------------- epilogue --------------------
    // n8-tiles never straddle segment boundaries (40/80/120 all multiples of 8)
#pragma unroll
    for (int nt = 0; nt < 8; nt++) {
        int col = wn * 64 + nt * 8 + 2 * tig;
        if (col >= 120) continue;
        int seg = col / 40;
        int cb  = col - seg * 40;
        float* base = (seg == 0) ? out : (seg == 1) ? g_g1 : g_g2;
        float b0 = 0.f, b1v = 0.f;
        if (seg == 0) {
            b0  = __ldg(bias + cb);
            b1v = __ldg(bias + cb + 1);
        }
#pragma unroll
        for (int mt = 0; mt < 2; mt++) {
            int r_lo = row0 + wm * 32 + mt * 16 + grp;
            int r_hi = r_lo + 8;
            if (r_lo < NN)
                *reinterpret_cast<float2*>(base + (size_t)r_lo * OC + cb) =
                    make_float2(c2[mt][nt][0] + b0, c2[mt][nt][1] + b1v);
            if (r_hi < NN)
                *reinterpret_cast<float2*>(base + (size_t)r_hi * OC + cb) =
                    make_float2(c2[mt][nt][2] + b0, c2[mt][nt][3] + b1v);
        }
    }
}

// ---------------------------------------------------------------------------
// Binning: zero counters -> scatter (4 edges/thread, vectorized loads).
// ---------------------------------------------------------------------------
__global__ void zero_cnt() {
    int i = blockIdx.x * blockDim.x + threadIdx.x;
    if (i < NN)          g_cnt1[i] = 0;
    else if (i < 2 * NN) g_cnt2[i - NN] = 0;
    if (i == 0) g_ovf_n = 0;
}

__device__ __forceinline__ void scat1(int r, int c, float vf, int2* slots,
                                      int* cnt, int maxd, int gflag) {
    int v = __float_as_int(vf);
    int p = atomicAdd(&cnt[r], 1);
    if (p < maxd) {
        slots[(size_t)r * maxd + p] = make_int2(c, v);
    } else {
        int o = atomicAdd(&g_ovf_n, 1);
        if (o < OVFMAX) g_ovf[o] = make_int4(gflag, r, c, v);
    }
}

__global__ void scatter(const int* __restrict__ r1, const int* __restrict__ c1,
                        const float* __restrict__ v1, int E1,
                        const int* __restrict__ r2, const int* __restrict__ c2,
                        const float* __restrict__ v2, int E2) {
    int t = blockIdx.x * blockDim.x + threadIdx.x;
    int q1 = (E1 + 3) >> 2;
    int q2 = (E2 + 3) >> 2;
    const int* R; const int* C; const float* V;
    int2* slots; int* cnt; int maxd, gflag, E, base;
    if (t < q1) {
        R = r1; C = c1; V = v1; E = E1; base = t * 4;
        slots = g_slot1; cnt = g_cnt1; maxd = MAXD1; gflag = 0;
    } else if (t < q1 + q2) {
        R = r2; C = c2; V = v2; E = E2; base = (t - q1) * 4;
        slots = g_slot2; cnt = g_cnt2; maxd = MAXD2; gflag = 1;
    } else return;

    if (base + 4 <= E) {
        int4   rr = __ldg(reinterpret_cast<const int4*>(R + base));
        int4   cc = __ldg(reinterpret_cast<const int4*>(C + base));
        float4 vv = __ldg(reinterpret_cast<const float4*>(V + base));
        scat1(rr.x, cc.x, vv.x, slots, cnt, maxd, gflag);
        scat1(rr.y, cc.y, vv.y, slots, cnt, maxd, gflag);
        scat1(rr.z, cc.z, vv.z, slots, cnt, maxd, gflag);
        scat1(rr.w, cc.w, vv.w, slots, cnt, maxd, gflag);
    } else {
        for (int j = base; j < E; j++)
            scat1(__ldg(R + j), __ldg(C + j), __ldg(V + j), slots, cnt, maxd, gflag);
    }
}

// ---------------------------------------------------------------------------
// GATHER: 2 warps per row (one per graph). Warp: 3 edges x 10 float4-lanes,
// unroll-2. Capture-first 3-way shfl combine, then one 10-lane red.v4.
// ---------------------------------------------------------------------------
__global__ __launch_bounds__(256) void gather(float* __restrict__ out) {
    const int w = (int)((blockIdx.x * blockDim.x + threadIdx.x) >> 5);
    if (w >= 2 * NN) return;
    const int r = w >> 1;
    const int g = w & 1;

    const int2*  slots;
    const float* G;
    int cnt;
    if (g == 0) {
        slots = g_slot1 + (size_t)r * MAXD1;
        G     = g_g1;
        cnt   = min(__ldg(&g_cnt1[r]), MAXD1);
    } else {
        slots = g_slot2 + (size_t)r * MAXD2;
        G     = g_g2;
        cnt   = min(__ldg(&g_cnt2[r]), MAXD2);
    }

    const int lane = threadIdx.x & 31;
    const int grp  = lane / 10;
    const int slot = lane - grp * 10;
    const bool act = lane < 30;

    float4 acc = make_float4(0.f, 0.f, 0.f, 0.f);
    if (act) {
        int e = grp;
        for (; e + 3 < cnt; e += 6) {
            int2 ea = __ldg(slots + e);
            int2 eb = __ldg(slots + e + 3);
            float4 ha = __ldg(reinterpret_cast<const float4*>(
                              G + (size_t)ea.x * OC + slot * 4));
            float4 hb = __ldg(reinterpret_cast<const float4*>(
                              G + (size_t)eb.x * OC + slot * 4));
            float va = __int_as_float(ea.y);
            float vb = __int_as_float(eb.y);
            acc.x += va * ha.x + vb * hb.x;
            acc.y += va * ha.y + vb * hb.y;
            acc.z += va * ha.z + vb * hb.z;
            acc.w += va * ha.w + vb * hb.w;
        }
        if (e < cnt) {
            int2 ea = __ldg(slots + e);
            float4 ha = __ldg(reinterpret_cast<const float4*>(
                              G + (size_t)ea.x * OC + slot * 4));
            float va = __int_as_float(ea.y);
            acc.x += va * ha.x; acc.y += va * ha.y;
            acc.z += va * ha.z; acc.w += va * ha.w;
        }
    }
    float4 b1, b2;
    b1.x = __shfl_down_sync(0xffffffffu, acc.x, 10);
    b1.y = __shfl_down_sync(0xffffffffu, acc.y, 10);
    b1.z = __shfl_down_sync(0xffffffffu, acc.z, 10);
    b1.w = __shfl_down_sync(0xffffffffu, acc.w, 10);
    b2.x = __shfl_down_sync(0xffffffffu, acc.x, 20);
    b2.y = __shfl_down_sync(0xffffffffu, acc.y, 20);
    b2.z = __shfl_down_sync(0xffffffffu, acc.z, 20);
    b2.w = __shfl_down_sync(0xffffffffu, acc.w, 20);

    if (lane < 10) {
        float* dst = out + (size_t)r * OC + slot * 4;
        float4 s = make_float4(acc.x + b1.x + b2.x, acc.y + b1.y + b2.y,
                               acc.z + b1.z + b2.z, acc.w + b1.w + b2.w);
        asm volatile("red.global.add.v4.f32 [%0], {%1,%2,%3,%4};"
                     :: "l"(dst), "f"(s.x), "f"(s.y), "f"(s.z), "f"(s.w)
                     : "memory");
    }
}

// ---------------------------------------------------------------------------
// FIXUP: process overflow edges (normally zero of them).
// ---------------------------------------------------------------------------
__global__ void fixup(float* __restrict__ out) {
    int n = g_ovf_n;
    if (n > OVFMAX) n = OVFMAX;
    for (int i = threadIdx.x; i < n; i += blockDim.x) {
        int4 e = g_ovf[i];
        const float* G = e.x ? g_g2 : g_g1;
        float v = __int_as_float(e.w);
        for (int j = 0; j < OC; j++) {
            float p = v * G[(size_t)e.z * OC + j];
            asm volatile("red.global.add.f32 [%0], %1;"
                         :: "l"(out + (size_t)e.y * OC + j), "f"(p) : "memory");
        }
    }
}

// ---------------------------------------------------------------------------
// Launch: zero -> scatter -> fused_gemm -> gather -> fixup
// ---------------------------------------------------------------------------
extern "C" void kernel_launch(void* const* d_in, const int* in_sizes, int n_in,
                              void* d_out, int out_size) {
    const float* x   = (const float*)d_in[0];
    const int*   a1r = (const int*)  d_in[2];
    const int*   a1c = (const int*)  d_in[3];
    const float* a1v = (const float*)d_in[4];
    const int*   a2r = (const int*)  d_in[5];
    const int*   a2c = (const int*)  d_in[6];
    const float* a2v = (const float*)d_in[7];
    const float* w1  = (const float*)d_in[8];
    const float* w2  = (const float*)d_in[9];
    const float* b2  = (const float*)d_in[10];
    float* out = (float*)d_out;
    const int E1 = in_sizes[4];
    const int E2 = in_sizes[7];

    cudaFuncSetAttribute(fused_gemm, cudaFuncAttributeMaxDynamicSharedMemorySize,
                         SMEM_BYTES);

    zero_cnt<<<(2 * NN + 255) / 256, 256>>>();
    {
        int q = ((E1 + 3) >> 2) + ((E2 + 3) >> 2);
        scatter<<<(q + 255) / 256, 256>>>(a1r, a1c, a1v, E1, a2r, a2c, a2v, E2);
    }
    fused_gemm<<<(NN + 127) / 128, 256, SMEM_BYTES>>>(x, w1, w2, b2, out);
    gather<<<(2 * NN * 32 + 255) / 256, 256>>>(out);
    fixup<<<1, 256>>>(out);
}